// round 3
// baseline (speedup 1.0000x reference)
#include <cuda_runtime.h>
#include <math.h>

#define NMAX_PAD (8192 + 1024)
#define TI 512
#define TJ 512
#define PTHREADS 256

// scratch (no allocations allowed)
__device__ float2 g_base[NMAX_PAD];
__device__ float2 g_tgt[NMAX_PAD];
// [0..3]: centroid sums bx,by,tx,ty   [4..6]: acc bb,tt,bt
__device__ float g_red[8];

__device__ __forceinline__ float ex2_approx(float x) {
    float y;
    asm("ex2.approx.f32 %0, %1;" : "=f"(y) : "f"(x));
    return y;
}

__global__ void zero_kernel() {
    if (threadIdx.x < 8) g_red[threadIdx.x] = 0.0f;
}

__device__ __forceinline__ float block_reduce(float v, float* sm) {
    // warp reduce
    #pragma unroll
    for (int o = 16; o > 0; o >>= 1) v += __shfl_xor_sync(0xFFFFFFFFu, v, o);
    int warp = threadIdx.x >> 5;
    int lane = threadIdx.x & 31;
    if (lane == 0) sm[warp] = v;
    __syncthreads();
    if (warp == 0) {
        v = (lane < (blockDim.x >> 5)) ? sm[lane] : 0.0f;
        #pragma unroll
        for (int o = 16; o > 0; o >>= 1) v += __shfl_xor_sync(0xFFFFFFFFu, v, o);
    }
    return v;  // valid on warp 0 lane 0
}

__global__ void centroid_kernel(const float* __restrict__ base,
                                const float* __restrict__ tgt,
                                const float* __restrict__ log_scale,
                                int N, int M) {
    __shared__ float sm[8];
    int cloud = blockIdx.y;
    const float* p = cloud ? tgt : base;
    int n = cloud ? M : N;
    float sx = __expf(log_scale[0]);
    float sy = __expf(log_scale[1]);
    int i = blockIdx.x * blockDim.x + threadIdx.x;
    float x = 0.0f, y = 0.0f;
    if (i < n) { x = p[2 * i] * sx; y = p[2 * i + 1] * sy; }
    float rx = block_reduce(x, sm);
    __syncthreads();
    float ry = block_reduce(y, sm);
    if (threadIdx.x == 0) {
        atomicAdd(&g_red[cloud * 2 + 0], rx);
        atomicAdd(&g_red[cloud * 2 + 1], ry);
    }
}

__global__ void center_kernel(const float* __restrict__ base,
                              const float* __restrict__ tgt,
                              const float* __restrict__ log_scale,
                              const float* __restrict__ log_sigma,
                              int N, int M, int NP, int MP) {
    float sx = __expf(log_scale[0]);
    float sy = __expf(log_scale[1]);
    float sig = __expf(log_sigma[0]);
    float inv2s2 = 0.5f / (sig * sig);
    float r = sqrtf(inv2s2 * 1.4426950408889634f);  // so -( (r dx)^2 + (r dy)^2 ) = -d^2*inv2s2*log2(e)
    int i = blockIdx.x * blockDim.x + threadIdx.x;
    if (blockIdx.y == 0) {
        if (i < NP) {
            float2 o;
            if (i < N) {
                float cx = g_red[0] / (float)N;
                float cy = g_red[1] / (float)N;
                o.x = (base[2 * i] * sx - cx) * r;
                o.y = (base[2 * i + 1] * sy - cy) * r;
            } else {
                // pad: far from everything; distinct pads far from each other.
                // pad vs real / pad vs other-cloud pad -> ex2(-inf)=0.
                // pad vs itself -> k=1 (subtracted analytically in final kernel).
                // pad vs other same-cloud pad -> dy>=1e6 -> ex2(-1e12)=0.
                o.x = 1e18f;
                o.y = (float)i * 1e6f;
            }
            g_base[i] = o;
        }
    } else {
        if (i < MP) {
            float2 o;
            if (i < M) {
                float cx = g_red[2] / (float)M;
                float cy = g_red[3] / (float)M;
                o.x = (tgt[2 * i] * sx - cx) * r;
                o.y = (tgt[2 * i + 1] * sy - cy) * r;
            } else {
                o.x = -1e18f;
                o.y = (float)i * 1e6f;
            }
            g_tgt[i] = o;
        }
    }
}

__global__ __launch_bounds__(PTHREADS) void pair_kernel(int NP, int MP) {
    int z = blockIdx.z;
    int it = blockIdx.y;
    int jt = blockIdx.x;

    const float2* I;
    const float2* J;
    int iTiles, jTiles;
    if (z == 0)      { I = g_base; J = g_base; iTiles = NP / TI; jTiles = NP / TJ; }
    else if (z == 1) { I = g_tgt;  J = g_tgt;  iTiles = MP / TI; jTiles = MP / TJ; }
    else             { I = g_base; J = g_tgt;  iTiles = NP / TI; jTiles = MP / TJ; }

    if (it >= iTiles || jt >= jTiles) return;
    if (z < 2 && jt < it) return;  // symmetry: only upper-triangle tiles

    __shared__ float2 sj[TJ];
    __shared__ float sred[8];

    int j0 = jt * TJ;
    for (int k = threadIdx.x; k < TJ; k += PTHREADS) sj[k] = J[j0 + k];
    __syncthreads();

    int i0 = it * TI + threadIdx.x;
    float2 p0 = I[i0];
    float2 p1 = I[i0 + PTHREADS];

    float a0 = 0.0f, a1 = 0.0f;
    #pragma unroll 8
    for (int j = 0; j < TJ; j++) {
        float2 q = sj[j];
        float dx0 = p0.x - q.x;
        float dy0 = p0.y - q.y;
        float dx1 = p1.x - q.x;
        float dy1 = p1.y - q.y;
        float s0 = -dx0 * dx0 - dy0 * dy0;  // FMUL(neg) + FFMA(neg)
        float s1 = -dx1 * dx1 - dy1 * dy1;
        a0 += ex2_approx(s0);
        a1 += ex2_approx(s1);
    }

    float total = block_reduce(a0 + a1, sred);
    if (threadIdx.x == 0) {
        float w = (z < 2 && it != jt) ? 2.0f : 1.0f;
        atomicAdd(&g_red[4 + z], total * w);
    }
}

__global__ void final_kernel(float* __restrict__ out, int N, int M, int NP, int MP) {
    float bb = g_red[4] - (float)(NP - N);  // remove pad self-pairs (k=1 each, diagonal tiles)
    float tt = g_red[5] - (float)(MP - M);
    float bt = g_red[6];
    float fN = (float)N, fM = (float)M;
    out[0] = bb / (fN * fN) + tt / (fM * fM) - 2.0f * bt / (fN * fM);
}

extern "C" void kernel_launch(void* const* d_in, const int* in_sizes, int n_in,
                              void* d_out, int out_size) {
    const float* base = (const float*)d_in[0];
    const float* tgt  = (const float*)d_in[1];
    const float* lsig = (const float*)d_in[2];
    const float* lsc  = (const float*)d_in[3];

    int N = in_sizes[0] / 2;
    int M = in_sizes[1] / 2;
    int NP = ((N + TI - 1) / TI) * TI;
    int MP = ((M + TI - 1) / TI) * TI;

    zero_kernel<<<1, 32>>>();

    int nmax = N > M ? N : M;
    centroid_kernel<<<dim3((nmax + 255) / 256, 2), 256>>>(base, tgt, lsc, N, M);

    int npmax = NP > MP ? NP : MP;
    center_kernel<<<dim3((npmax + 255) / 256, 2), 256>>>(base, tgt, lsc, lsig, N, M, NP, MP);

    int iT = NP / TI > MP / TI ? NP / TI : MP / TI;
    int jT = iT;
    pair_kernel<<<dim3(jT, iT, 3), PTHREADS>>>(NP, MP);

    final_kernel<<<1, 1>>>((float*)d_out, N, M, NP, MP);
}